// round 10
// baseline (speedup 1.0000x reference)
#include <cuda_runtime.h>
#include <cuda_fp16.h>
#include <mma.h>
#include <math.h>
using namespace nvcuda;

#define N_NODES 50000
#define N_PAD   50016     // multiple of 32
#define E_MAX   800000
#define SCAN_BLOCKS 196   // 196*256 = 50176 >= 50000

// div_term[i] = 10^(-i/4) = exp(-i*ln(10000)/16), i = 0..15 (exact table)
__constant__ float c_dv[16] = {
    1.0f, 0.5623413251903491f, 0.31622776601683794f, 0.17782794100389228f,
    0.1f, 0.05623413251903491f, 0.031622776601683794f, 0.017782794100389228f,
    0.01f, 0.005623413251903491f, 0.0031622776601683794f, 0.0017782794100389228f,
    0.001f, 0.0005623413251903491f, 0.00031622776601683794f, 0.00017782794100389228f};

// ---------------- static device scratch (zero-initialized, incl. pad rows) ----------------
__device__ float  g_q  [N_PAD * 128];
__device__ float  g_qt [N_PAD * 128];
__device__ float  g_qbt[N_PAD * 4];
__device__ __half g_kh [N_PAD * 128];   // k rows, head-contiguous
__device__ __half g_vh [N_PAD * 128];   // v rows
__device__ __half g_xh [N_PAD * 64];    // emb -> half
__device__ __half g_x1h[N_PAD * 128];   // layer-1 output (half), pad rows stay 0
__device__ float  g_xc [N_NODES];
__device__ __half g_w1 [3 * 64 * 128];  // wq1|wk1|wv1 as half
__device__ __half g_wt1[32 * 128];
__device__ __half g_w2 [3 * 128 * 128];
__device__ __half g_wt2[32 * 128];
__device__ int    g_deg[N_NODES];
__device__ int    g_cur[N_NODES];
__device__ int    g_off[N_NODES + 1];
__device__ int    g_bsum[SCAN_BLOCKS];
__device__ int    g_bpre[SCAN_BLOCKS];
__device__ int    g_sync[8];
__device__ int    g_ssrc[E_MAX];             // src node, sorted by dst
__device__ float  g_et [E_MAX];              // time, sorted by dst
__device__ __half g_tfh[(size_t)E_MAX * 32]; // fp16 time encoding, sorted (51MB)

// ---------------- merged setup: zero counters + all fp32->fp16 conversions ----------------
__global__ void setup_kernel(const float* __restrict__ emb,
                             const float* __restrict__ wq1, const float* __restrict__ wk1,
                             const float* __restrict__ wv1, const float* __restrict__ wt1,
                             const float* __restrict__ wq2, const float* __restrict__ wk2,
                             const float* __restrict__ wv2, const float* __restrict__ wt2) {
    int i = blockIdx.x * 256 + threadIdx.x;
    if (i < N_NODES * 64) g_xh[i] = __float2half(emb[i]);
    if (i < N_NODES) { g_deg[i] = 0; g_cur[i] = 0; }
    if (i < 8) g_sync[i] = 0;
    {
        const int per = 64 * 128;
        if (i < 3 * per) {
            const float* s = (i < per) ? wq1 : ((i < 2 * per) ? wk1 : wv1);
            g_w1[i] = __float2half(s[i % per]);
        }
    }
    {
        const int per = 128 * 128;
        if (i < 3 * per) {
            const float* s = (i < per) ? wq2 : ((i < 2 * per) ? wk2 : wv2);
            g_w2[i] = __float2half(s[i % per]);
        }
    }
    if (i < 32 * 128) {
        g_wt1[i] = __float2half(wt1[i]);
        g_wt2[i] = __float2half(wt2[i]);
    }
}

// ---------------- fused counting sort + tfeat ----------------
__device__ __forceinline__ void grid_arrive_wait(int* ctr, int target) {
    __threadfence();
    __syncthreads();
    if (threadIdx.x == 0) {
        atomicAdd(ctr, 1);
        while (atomicAdd(ctr, 0) < target) { }
    }
    __syncthreads();
    __threadfence();
}

__global__ __launch_bounds__(256) void sortscan_kernel(const int* __restrict__ ei,
                                                       const float* __restrict__ ea, int E) {
    __shared__ int sh[256];
    const int t = threadIdx.x;
    const int b = blockIdx.x;

    // phase 0: histogram (grid-stride)
    for (int e = b * 256 + t; e < E; e += SCAN_BLOCKS * 256)
        atomicAdd(&g_deg[ei[E + e]], 1);
    grid_arrive_wait(&g_sync[0], SCAN_BLOCKS);

    // phase A: block-local exclusive scan
    int i = b * 256 + t;
    int v = (i < N_NODES) ? g_deg[i] : 0;
    sh[t] = v;
    __syncthreads();
    for (int o = 1; o < 256; o <<= 1) {
        int u = (t >= o) ? sh[t - o] : 0;
        __syncthreads();
        sh[t] += u;
        __syncthreads();
    }
    int local_ex = sh[t] - v;
    if (t == 255) g_bsum[b] = sh[255];
    grid_arrive_wait(&g_sync[1], SCAN_BLOCKS);

    // phase B: block 0 scans block totals
    if (b == 0) {
        int bv = (t < SCAN_BLOCKS) ? g_bsum[t] : 0;
        sh[t] = bv;
        __syncthreads();
        for (int o = 1; o < 256; o <<= 1) {
            int u = (t >= o) ? sh[t - o] : 0;
            __syncthreads();
            sh[t] += u;
            __syncthreads();
        }
        if (t < SCAN_BLOCKS) g_bpre[t] = sh[t] - bv;
        if (t == 255) g_off[N_NODES] = sh[255];
        __threadfence();
        __syncthreads();
        if (t == 0) atomicExch(&g_sync[2], 1);
    }
    if (t == 0) while (atomicAdd(&g_sync[2], 0) == 0) { }
    __syncthreads();
    __threadfence();

    // phase C: final offsets
    if (i < N_NODES) g_off[i] = local_ex + g_bpre[b];
    grid_arrive_wait(&g_sync[3], SCAN_BLOCKS);

    // phase D: scatter edges into dst-sorted order
    for (int e = b * 256 + t; e < E; e += SCAN_BLOCKS * 256) {
        int d = ei[E + e];
        int pos = g_off[d] + atomicAdd(&g_cur[d], 1);
        g_ssrc[pos] = ei[e];
        g_et[pos]   = ea[2 * e + 1];
    }
    grid_arrive_wait(&g_sync[4], SCAN_BLOCKS);

    // phase E: fp16 time encoding in sorted order
    for (int e = b * 256 + t; e < E; e += SCAN_BLOCKS * 256) {
        float tv = g_et[e];
        uint4 out[2];
        unsigned* o32 = reinterpret_cast<unsigned*>(out);
#pragma unroll
        for (int p = 0; p < 16; p++) {
            float a = tv * c_dv[p];
            __half2 h = __floats2half2_rn(__sinf(a), __cosf(a));
            o32[p] = *reinterpret_cast<unsigned*>(&h);
        }
        uint4* dst = reinterpret_cast<uint4*>(g_tfh + (size_t)e * 32);
        dst[0] = out[0];
        dst[1] = out[1];
    }
}

// ---------------- tensor-core node linear: q, k, v(fp16), qt, qbt ----------------
template <int L>
__global__ __launch_bounds__(256) void node_linear_wmma(
    const float* __restrict__ bq, const float* __restrict__ bk,
    const float* __restrict__ bv, const float* __restrict__ bt)
{
    constexpr int D = (L == 0) ? 64 : 128;
    const __half* __restrict__ xh  = (L == 0) ? g_xh  : g_x1h;
    const __half* __restrict__ wh  = (L == 0) ? g_w1  : g_w2;
    const __half* __restrict__ wth = (L == 0) ? g_wt1 : g_wt2;

    __shared__ float  stage[32 * 128];   // 16 KB
    __shared__ __half qsh[32 * 128];     // 8 KB
    __shared__ __half ksh[32 * 128];     // 8 KB
    __shared__ __half vsh[32 * 128];     // 8 KB
    const int w = threadIdx.x >> 5;
    const int node0 = blockIdx.x * 32;

    wmma::fragment<wmma::accumulator, 16, 16, 16, float> acc[3][2];
#pragma unroll
    for (int m = 0; m < 3; m++)
#pragma unroll
        for (int r = 0; r < 2; r++) wmma::fill_fragment(acc[m][r], 0.f);

#pragma unroll
    for (int k0 = 0; k0 < D; k0 += 16) {
        wmma::fragment<wmma::matrix_a, 16, 16, 16, __half, wmma::row_major> a0, a1;
        wmma::load_matrix_sync(a0, xh + (size_t)node0 * D + k0, D);
        wmma::load_matrix_sync(a1, xh + (size_t)(node0 + 16) * D + k0, D);
#pragma unroll
        for (int m = 0; m < 3; m++) {
            wmma::fragment<wmma::matrix_b, 16, 16, 16, __half, wmma::row_major> b;
            wmma::load_matrix_sync(b, wh + m * (D * 128) + k0 * 128 + w * 16, 128);
            wmma::mma_sync(acc[m][0], a0, b, acc[m][0]);
            wmma::mma_sync(acc[m][1], a1, b, acc[m][1]);
        }
    }

    const float inv = 0.17677669529663688f;  // 1/sqrt(32)
#pragma unroll
    for (int m = 0; m < 3; m++) {
        wmma::store_matrix_sync(stage + w * 16, acc[m][0], 128, wmma::mem_row_major);
        wmma::store_matrix_sync(stage + 16 * 128 + w * 16, acc[m][1], 128, wmma::mem_row_major);
        __syncthreads();
        for (int i = threadIdx.x; i < 32 * 128; i += 256) {
            int c = i & 127;
            int node = node0 + (i >> 7);
            float val = stage[i];
            if (m == 0) {
                float qv = (val + bq[c]) * inv;
                qsh[i] = __float2half(qv);
                g_q[(size_t)node * 128 + c] = qv;
            } else if (m == 1) {
                ksh[i] = __float2half(val + bk[c]);
            } else {
                vsh[i] = __float2half(val + bv[c]);
            }
        }
        __syncthreads();
    }

    // coalesced copy of k, v tiles to global (row layout, head-contiguous)
    for (int idx = threadIdx.x; idx < 512; idx += 256) {  // 512 uint4 = 32 rows x 256B
        reinterpret_cast<uint4*>(g_kh + (size_t)node0 * 128)[idx] =
            reinterpret_cast<const uint4*>(ksh)[idx];
        reinterpret_cast<uint4*>(g_vh + (size_t)node0 * 128)[idx] =
            reinterpret_cast<const uint4*>(vsh)[idx];
    }

    // qt GEMM: per-head 32x32; warp w -> head h = w>>1, col offset d0 = (w&1)*16
    {
        int h = w >> 1, d0 = (w & 1) * 16;
        wmma::fragment<wmma::accumulator, 16, 16, 16, float> q0, q1;
        wmma::fill_fragment(q0, 0.f);
        wmma::fill_fragment(q1, 0.f);
#pragma unroll
        for (int k0 = 0; k0 < 32; k0 += 16) {
            wmma::fragment<wmma::matrix_a, 16, 16, 16, __half, wmma::row_major> a0, a1;
            wmma::fragment<wmma::matrix_b, 16, 16, 16, __half, wmma::col_major> b;
            wmma::load_matrix_sync(a0, qsh + h * 32 + k0, 128);
            wmma::load_matrix_sync(a1, qsh + 16 * 128 + h * 32 + k0, 128);
            wmma::load_matrix_sync(b, wth + h * 32 + k0 + d0 * 128, 128);
            wmma::mma_sync(q0, a0, b, q0);
            wmma::mma_sync(q1, a1, b, q1);
        }
        wmma::store_matrix_sync(g_qt + (size_t)node0 * 128 + h * 32 + d0, q0, 128, wmma::mem_row_major);
        wmma::store_matrix_sync(g_qt + (size_t)(node0 + 16) * 128 + h * 32 + d0, q1, 128, wmma::mem_row_major);
    }

    // qbt: node n, head hh -> dot(q'[n, hh*32:+32], bt[hh*32:+32])
    if (threadIdx.x < 128) {
        int n = threadIdx.x >> 2, hh = threadIdx.x & 3;
        float b = 0.f;
#pragma unroll
        for (int c = 0; c < 32; c++)
            b = fmaf(__half2float(qsh[n * 128 + hh * 32 + c]), bt[hh * 32 + c], b);
        g_qbt[(size_t)(node0 + n) * 4 + hh] = b;
    }
}

// ---------------- per-node softmax aggregation ----------------
// New mapping: lane = head*8 + edge_sub. Each lane computes the FULL 32-dim
// alpha for its (edge, head) over batches of 8 edges; v-accumulation runs in
// the per-lane-4-dims layout with pe broadcast (1 shfl/edge). Raw exp (no ref):
// softmax is shift-invariant and alphas are O(0.1) here; clamp + s-guard anyway.
__device__ __forceinline__ float dot8(uint4 kk, float4 qa, float4 qb, float p) {
    float2 x0 = __half22float2(*reinterpret_cast<__half2*>(&kk.x));
    float2 x1 = __half22float2(*reinterpret_cast<__half2*>(&kk.y));
    float2 x2 = __half22float2(*reinterpret_cast<__half2*>(&kk.z));
    float2 x3 = __half22float2(*reinterpret_cast<__half2*>(&kk.w));
    p = fmaf(qa.x, x0.x, p); p = fmaf(qa.y, x0.y, p);
    p = fmaf(qa.z, x1.x, p); p = fmaf(qa.w, x1.y, p);
    p = fmaf(qb.x, x2.x, p); p = fmaf(qb.y, x2.y, p);
    p = fmaf(qb.z, x3.x, p); p = fmaf(qb.w, x3.y, p);
    return p;
}

template <int LAYER>
__global__ __launch_bounds__(128) void edge_agg_kernel(const float* __restrict__ wc) {
    const int lane = threadIdx.x & 31;
    const int node = blockIdx.x * 4 + (threadIdx.x >> 5);
    if (node >= N_NODES) return;

    const int start = g_off[node], end = g_off[node + 1];
    if (start >= end) {
        if (LAYER == 0) {
            reinterpret_cast<uint2*>(g_x1h + (size_t)node * 128)[lane] = make_uint2(0u, 0u);
        } else if (lane == 0) {
            g_xc[node] = 0.f;
        }
        return;
    }

    const int h  = lane >> 3;   // head for the dot phase (also v-dims head)
    const int es = lane & 7;    // edge slot within batch

    // resident: full q,qt rows for this head (32 dims each)
    float4 qr[8], qtr[8];
    {
        const float4* qp  = reinterpret_cast<const float4*>(g_q  + (size_t)node * 128 + h * 32);
        const float4* qtp = reinterpret_cast<const float4*>(g_qt + (size_t)node * 128 + h * 32);
#pragma unroll
        for (int c = 0; c < 8; c++) { qr[c] = qp[c]; qtr[c] = qtp[c]; }
    }
    const float qbt = g_qbt[(size_t)node * 4 + h];

    float4 acc = make_float4(0.f, 0.f, 0.f, 0.f);
    float s = 0.f;

    for (int base = start; base < end; base += 8) {
        int idx = base + es;
        bool valid = idx < end;
        int myi = valid ? idx : (end - 1);
        int msrc = g_ssrc[myi];

        // full 32-dim alpha dot for (edge=myi, head=h)
        const uint4* kp = reinterpret_cast<const uint4*>(g_kh + (size_t)msrc * 128 + h * 32);
        const uint4* tp = reinterpret_cast<const uint4*>(g_tfh + (size_t)myi * 32);
        float p = qbt;
#pragma unroll
        for (int c = 0; c < 4; c++) {
            p = dot8(kp[c], qr [2 * c], qr [2 * c + 1], p);
            p = dot8(tp[c], qtr[2 * c], qtr[2 * c + 1], p);
        }
        float pe = valid ? __expf(fminf(p, 80.f)) : 0.f;

        // v accumulation: per-lane 4 dims (lane*4..+3), pe broadcast per edge
#pragma unroll
        for (int e = 0; e < 8; e++) {
            float pe_e  = __shfl_sync(0xffffffffu, pe, (lane & 24) | e);
            int   src_e = __shfl_sync(0xffffffffu, msrc, e);   // head0 lanes hold srcs
            uint2 vr = *reinterpret_cast<const uint2*>(g_vh + (size_t)src_e * 128 + lane * 4);
            float2 v01 = __half22float2(*reinterpret_cast<__half2*>(&vr.x));
            float2 v23 = __half22float2(*reinterpret_cast<__half2*>(&vr.y));
            s += pe_e;
            acc.x = fmaf(pe_e, v01.x, acc.x);
            acc.y = fmaf(pe_e, v01.y, acc.y);
            acc.z = fmaf(pe_e, v23.x, acc.z);
            acc.w = fmaf(pe_e, v23.y, acc.w);
        }
    }

    float r = 1.f / (s + 1e-37f);
    float4 o = make_float4(fmaxf(acc.x * r, 0.f), fmaxf(acc.y * r, 0.f),
                           fmaxf(acc.z * r, 0.f), fmaxf(acc.w * r, 0.f));

    if (LAYER == 0) {
        __half2 h01 = __floats2half2_rn(o.x, o.y);
        __half2 h23 = __floats2half2_rn(o.z, o.w);
        uint2 u;
        u.x = *reinterpret_cast<unsigned*>(&h01);
        u.y = *reinterpret_cast<unsigned*>(&h23);
        reinterpret_cast<uint2*>(g_x1h + (size_t)node * 128)[lane] = u;
    } else {
        // fused classifier: xc[node] = relu(x2_row) . wc
        float4 w4 = reinterpret_cast<const float4*>(wc)[lane];
        float p = o.x * w4.x;
        p = fmaf(o.y, w4.y, p);
        p = fmaf(o.z, w4.z, p);
        p = fmaf(o.w, w4.w, p);
#pragma unroll
        for (int off = 16; off; off >>= 1)
            p += __shfl_xor_sync(0xffffffffu, p, off);
        if (lane == 0) g_xc[node] = p;
    }
}

// ---------------- final: out[e] = xc[src] + xc[dst] + bc ----------------
__global__ void final_kernel(const int* __restrict__ ei, const float* __restrict__ bc,
                             float* __restrict__ out, int E) {
    int e = blockIdx.x * blockDim.x + threadIdx.x;
    if (e >= E) return;
    out[e] = g_xc[ei[e]] + g_xc[ei[E + e]] + bc[0];
}

// ---------------- launch ----------------
extern "C" void kernel_launch(void* const* d_in, const int* in_sizes, int n_in,
                              void* d_out, int out_size) {
    const int*   ei  = (const int*)  d_in[0];
    const float* ea  = (const float*)d_in[1];
    const float* emb = (const float*)d_in[3];
    const float *wq1 = (const float*)d_in[4],  *bq1 = (const float*)d_in[5];
    const float *wk1 = (const float*)d_in[6],  *bk1 = (const float*)d_in[7];
    const float *wv1 = (const float*)d_in[8],  *bv1 = (const float*)d_in[9];
    const float *wt1 = (const float*)d_in[10], *bt1 = (const float*)d_in[11];
    const float *wq2 = (const float*)d_in[12], *bq2 = (const float*)d_in[13];
    const float *wk2 = (const float*)d_in[14], *bk2 = (const float*)d_in[15];
    const float *wv2 = (const float*)d_in[16], *bv2 = (const float*)d_in[17];
    const float *wt2 = (const float*)d_in[18], *bt2 = (const float*)d_in[19];
    const float *wc  = (const float*)d_in[20], *bc  = (const float*)d_in[21];
    float* out = (float*)d_out;

    int E = in_sizes[0] / 2;

    setup_kernel<<<(N_NODES * 64 + 255) / 256, 256>>>(emb, wq1, wk1, wv1, wt1,
                                                      wq2, wk2, wv2, wt2);        // 0
    sortscan_kernel<<<SCAN_BLOCKS, 256>>>(ei, ea, E);                             // 1
    node_linear_wmma<0><<<N_PAD / 32, 256>>>(bq1, bk1, bv1, bt1);                 // 2
    edge_agg_kernel<0><<<(N_NODES + 3) / 4, 128>>>(wc);                           // 3 <- profiled
    node_linear_wmma<1><<<N_PAD / 32, 256>>>(bq2, bk2, bv2, bt2);                 // 4
    edge_agg_kernel<1><<<(N_NODES + 3) / 4, 128>>>(wc);                           // 5
    final_kernel<<<(E + 255) / 256, 256>>>(ei, bc, out, E);                       // 6
}

// round 11
// speedup vs baseline: 1.3132x; 1.3132x over previous
#include <cuda_runtime.h>
#include <cuda_fp16.h>
#include <mma.h>
#include <math.h>
using namespace nvcuda;

#define N_NODES 50000
#define N_PAD   50016     // multiple of 32
#define E_MAX   800000
#define SCAN_BLOCKS 196   // 196*256 = 50176 >= 50000

// div_term[i] = 10^(-i/4) = exp(-i*ln(10000)/16), i = 0..15 (exact table)
__constant__ float c_dv[16] = {
    1.0f, 0.5623413251903491f, 0.31622776601683794f, 0.17782794100389228f,
    0.1f, 0.05623413251903491f, 0.031622776601683794f, 0.017782794100389228f,
    0.01f, 0.005623413251903491f, 0.0031622776601683794f, 0.0017782794100389228f,
    0.001f, 0.0005623413251903491f, 0.00031622776601683794f, 0.00017782794100389228f};

// ---------------- static device scratch (zero-initialized, incl. pad rows) ----------------
__device__ float  g_q  [N_PAD * 128];
__device__ __half g_kh [N_PAD * 128];
__device__ __half g_vh [N_PAD * 128];
__device__ float  g_qt [N_PAD * 128];
__device__ float  g_qbt[N_PAD * 4];
__device__ __half g_xh [N_PAD * 64];    // emb -> half
__device__ __half g_x1h[N_PAD * 128];   // layer-1 output (half), pad rows stay 0
__device__ float  g_xc [N_NODES];
__device__ __half g_w1 [3 * 64 * 128];  // wq1|wk1|wv1 as half
__device__ __half g_wt1[32 * 128];
__device__ __half g_w2 [3 * 128 * 128];
__device__ __half g_wt2[32 * 128];
__device__ int    g_deg[N_NODES];
__device__ int    g_cur[N_NODES];
__device__ int    g_off[N_NODES + 1];
__device__ int    g_bsum[SCAN_BLOCKS];
__device__ int    g_bpre[SCAN_BLOCKS];
__device__ int    g_ssrc[E_MAX];   // src node, sorted by dst
__device__ float  g_et  [E_MAX];   // time value, sorted by dst

// ---------------- fp32 -> fp16 conversions ----------------
__global__ void conv_emb_kernel(const float* __restrict__ emb) {
    int i = blockIdx.x * 256 + threadIdx.x;
    if (i < N_NODES * 64) g_xh[i] = __float2half(emb[i]);
}

template <int L>
__global__ void convw_kernel(const float* __restrict__ wq, const float* __restrict__ wk,
                             const float* __restrict__ wv, const float* __restrict__ wt) {
    constexpr int D = (L == 0) ? 64 : 128;
    __half* __restrict__ wdst  = (L == 0) ? g_w1  : g_w2;
    __half* __restrict__ wtdst = (L == 0) ? g_wt1 : g_wt2;
    int i = blockIdx.x * 256 + threadIdx.x;
    const int per = D * 128;
    if (i < 3 * per) {
        const float* s = (i < per) ? wq : ((i < 2 * per) ? wk : wv);
        wdst[i] = __float2half(s[i % per]);
    }
    if (i < 32 * 128) wtdst[i] = __float2half(wt[i]);
}

// ---------------- counting sort of edges by dst ----------------
__global__ void zero_kernel() {
    int i = blockIdx.x * blockDim.x + threadIdx.x;
    if (i < N_NODES) { g_deg[i] = 0; g_cur[i] = 0; }
}

__global__ void hist_kernel(const int* __restrict__ ei, int E) {
    int e = blockIdx.x * blockDim.x + threadIdx.x;
    if (e < E) atomicAdd(&g_deg[ei[E + e]], 1);
}

__global__ void scanA_kernel(int n) {
    __shared__ int sh[256];
    int t = threadIdx.x;
    int i = blockIdx.x * 256 + t;
    int v = (i < n) ? g_deg[i] : 0;
    sh[t] = v;
    __syncthreads();
    for (int o = 1; o < 256; o <<= 1) {
        int u = (t >= o) ? sh[t - o] : 0;
        __syncthreads();
        sh[t] += u;
        __syncthreads();
    }
    if (i < n) g_off[i] = sh[t] - v;
    if (t == 255) g_bsum[blockIdx.x] = sh[255];
}

__global__ void scanB_kernel(int nb, int n) {
    __shared__ int sh[256];
    int t = threadIdx.x;
    int v = (t < nb) ? g_bsum[t] : 0;
    sh[t] = v;
    __syncthreads();
    for (int o = 1; o < 256; o <<= 1) {
        int u = (t >= o) ? sh[t - o] : 0;
        __syncthreads();
        sh[t] += u;
        __syncthreads();
    }
    if (t < nb) g_bpre[t] = sh[t] - v;
    if (t == 255) g_off[n] = sh[255];
}

__global__ void scanC_kernel(int n) {
    int i = blockIdx.x * 256 + threadIdx.x;
    if (i < n) g_off[i] += g_bpre[blockIdx.x];
}

__global__ void scatter_kernel(const int* __restrict__ ei,
                               const float* __restrict__ ea, int E) {
    int e = blockIdx.x * blockDim.x + threadIdx.x;
    if (e >= E) return;
    int d = ei[E + e];
    int pos = g_off[d] + atomicAdd(&g_cur[d], 1);
    g_ssrc[pos] = ei[e];
    g_et[pos]   = ea[2 * e + 1];
}

// ---------------- tensor-core node linear: q, k(fp16), v(fp16), qt, qbt ----------------
template <int L>
__global__ __launch_bounds__(256) void node_linear_wmma(
    const float* __restrict__ bq, const float* __restrict__ bk,
    const float* __restrict__ bv, const float* __restrict__ bt)
{
    constexpr int D = (L == 0) ? 64 : 128;
    const __half* __restrict__ xh  = (L == 0) ? g_xh  : g_x1h;
    const __half* __restrict__ wh  = (L == 0) ? g_w1  : g_w2;
    const __half* __restrict__ wth = (L == 0) ? g_wt1 : g_wt2;

    __shared__ float  stage[32 * 128];   // 16 KB
    __shared__ __half qsh[32 * 128];     // 8 KB
    const int w = threadIdx.x >> 5;
    const int node0 = blockIdx.x * 32;

    wmma::fragment<wmma::accumulator, 16, 16, 16, float> acc[3][2];
#pragma unroll
    for (int m = 0; m < 3; m++)
#pragma unroll
        for (int r = 0; r < 2; r++) wmma::fill_fragment(acc[m][r], 0.f);

#pragma unroll
    for (int k0 = 0; k0 < D; k0 += 16) {
        wmma::fragment<wmma::matrix_a, 16, 16, 16, __half, wmma::row_major> a0, a1;
        wmma::load_matrix_sync(a0, xh + (size_t)node0 * D + k0, D);
        wmma::load_matrix_sync(a1, xh + (size_t)(node0 + 16) * D + k0, D);
#pragma unroll
        for (int m = 0; m < 3; m++) {
            wmma::fragment<wmma::matrix_b, 16, 16, 16, __half, wmma::row_major> b;
            wmma::load_matrix_sync(b, wh + m * (D * 128) + k0 * 128 + w * 16, 128);
            wmma::mma_sync(acc[m][0], a0, b, acc[m][0]);
            wmma::mma_sync(acc[m][1], a1, b, acc[m][1]);
        }
    }

    const float inv = 0.17677669529663688f;  // 1/sqrt(32)
#pragma unroll
    for (int m = 0; m < 3; m++) {
        wmma::store_matrix_sync(stage + w * 16, acc[m][0], 128, wmma::mem_row_major);
        wmma::store_matrix_sync(stage + 16 * 128 + w * 16, acc[m][1], 128, wmma::mem_row_major);
        __syncthreads();
        for (int i = threadIdx.x; i < 32 * 128; i += 256) {
            int c = i & 127;
            int node = node0 + (i >> 7);
            float val = stage[i];
            if (m == 0) {
                float qv = (val + bq[c]) * inv;
                qsh[i] = __float2half(qv);
                g_q[(size_t)node * 128 + c] = qv;
            } else if (m == 1) {
                g_kh[(size_t)node * 128 + c] = __float2half(val + bk[c]);
            } else {
                g_vh[(size_t)node * 128 + c] = __float2half(val + bv[c]);
            }
        }
        __syncthreads();
    }

    // qt GEMM: per-head 32x32; warp w -> head h = w>>1, col offset d0 = (w&1)*16
    {
        int h = w >> 1, d0 = (w & 1) * 16;
        wmma::fragment<wmma::accumulator, 16, 16, 16, float> q0, q1;
        wmma::fill_fragment(q0, 0.f);
        wmma::fill_fragment(q1, 0.f);
#pragma unroll
        for (int k0 = 0; k0 < 32; k0 += 16) {
            wmma::fragment<wmma::matrix_a, 16, 16, 16, __half, wmma::row_major> a0, a1;
            wmma::fragment<wmma::matrix_b, 16, 16, 16, __half, wmma::col_major> b;
            wmma::load_matrix_sync(a0, qsh + h * 32 + k0, 128);
            wmma::load_matrix_sync(a1, qsh + 16 * 128 + h * 32 + k0, 128);
            wmma::load_matrix_sync(b, wth + h * 32 + k0 + d0 * 128, 128);
            wmma::mma_sync(q0, a0, b, q0);
            wmma::mma_sync(q1, a1, b, q1);
        }
        wmma::store_matrix_sync(g_qt + (size_t)node0 * 128 + h * 32 + d0, q0, 128, wmma::mem_row_major);
        wmma::store_matrix_sync(g_qt + (size_t)(node0 + 16) * 128 + h * 32 + d0, q1, 128, wmma::mem_row_major);
    }

    // qbt: node n, head hh -> dot(q'[n, hh*32:+32], bt[hh*32:+32])
    if (threadIdx.x < 128) {
        int n = threadIdx.x >> 2, hh = threadIdx.x & 3;
        float b = 0.f;
#pragma unroll
        for (int c = 0; c < 32; c++)
            b = fmaf(__half2float(qsh[n * 128 + hh * 32 + c]), bt[hh * 32 + c], b);
        g_qbt[(size_t)(node0 + n) * 4 + hh] = b;
    }
}

// ---------------- per-node softmax aggregation (warp = node, 4 heads) ----------------
__device__ __forceinline__ float head_alpha(float4 q4, float4 qt4,
                                            float2 k01, float2 k23,
                                            float t, float dva, float dvb) {
    float a0 = t * dva, a1 = t * dvb;
    float p = q4.x * k01.x;
    p = fmaf(q4.y,  k01.y, p);
    p = fmaf(q4.z,  k23.x, p);
    p = fmaf(q4.w,  k23.y, p);
    p = fmaf(qt4.x, __sinf(a0), p);
    p = fmaf(qt4.y, __cosf(a0), p);
    p = fmaf(qt4.z, __sinf(a1), p);
    p = fmaf(qt4.w, __cosf(a1), p);
    p += __shfl_xor_sync(0xffffffffu, p, 4);
    p += __shfl_xor_sync(0xffffffffu, p, 2);
    p += __shfl_xor_sync(0xffffffffu, p, 1);
    return p;
}

template <int LAYER>
__global__ __launch_bounds__(256, 6) void edge_agg_kernel(const float* __restrict__ wc) {
    int lane = threadIdx.x & 31;
    int node = blockIdx.x * 8 + (threadIdx.x >> 5);
    if (node >= N_NODES) return;

    int idx = g_off[node], end = g_off[node + 1];
    if (idx >= end) {
        if (LAYER == 0) {
            reinterpret_cast<uint2*>(g_x1h + (size_t)node * 128)[lane] = make_uint2(0u, 0u);
        } else if (lane == 0) {
            g_xc[node] = 0.f;
        }
        return;
    }

    float4 q4  = reinterpret_cast<const float4*>(g_q  + (size_t)node * 128)[lane];
    float4 qt4 = reinterpret_cast<const float4*>(g_qt + (size_t)node * 128)[lane];
    float qbt  = g_qbt[(size_t)node * 4 + (lane >> 3)];

    int j = lane & 7;
    float dva = c_dv[2 * j];
    float dvb = c_dv[2 * j + 1];

    const float2* kh = reinterpret_cast<const float2*>(g_kh);
    const float2* vh = reinterpret_cast<const float2*>(g_vh);

    float s;
    float4 acc;
    float qbtr;   // qbt - ref, folded
    {   // peel first edge: reference point for exp
        int cs = g_ssrc[idx];
        float t = g_et[idx];
        float2 kraw = kh[(size_t)cs * 32 + lane];
        float2 vraw = vh[(size_t)cs * 32 + lane];
        float2 k01 = __half22float2(*reinterpret_cast<__half2*>(&kraw.x));
        float2 k23 = __half22float2(*reinterpret_cast<__half2*>(&kraw.y));
        float2 v01 = __half22float2(*reinterpret_cast<__half2*>(&vraw.x));
        float2 v23 = __half22float2(*reinterpret_cast<__half2*>(&vraw.y));
        float ref = head_alpha(q4, qt4, k01, k23, t, dva, dvb) + qbt;
        qbtr = qbt - ref;
        s = 1.f;
        acc = make_float4(v01.x, v01.y, v23.x, v23.y);
    }
    idx++;

    int cs = 0; float t = 0.f;
    if (idx < end) { cs = g_ssrc[idx]; t = g_et[idx]; }  // prefetch
#pragma unroll 2
    for (; idx < end; idx++) {
        int   ccs = cs;
        float ct  = t;
        if (idx + 1 < end) { cs = g_ssrc[idx + 1]; t = g_et[idx + 1]; }
        float2 kraw = kh[(size_t)ccs * 32 + lane];
        float2 vraw = vh[(size_t)ccs * 32 + lane];
        float2 k01 = __half22float2(*reinterpret_cast<__half2*>(&kraw.x));
        float2 k23 = __half22float2(*reinterpret_cast<__half2*>(&kraw.y));
        float2 v01 = __half22float2(*reinterpret_cast<__half2*>(&vraw.x));
        float2 v23 = __half22float2(*reinterpret_cast<__half2*>(&vraw.y));
        float alpha = head_alpha(q4, qt4, k01, k23, ct, dva, dvb) + qbtr;
        float pe = __expf(fminf(alpha, 80.f));
        s += pe;
        acc.x = fmaf(pe, v01.x, acc.x);
        acc.y = fmaf(pe, v01.y, acc.y);
        acc.z = fmaf(pe, v23.x, acc.z);
        acc.w = fmaf(pe, v23.y, acc.w);
    }

    float r = 1.f / s;
    float4 o = make_float4(fmaxf(acc.x * r, 0.f), fmaxf(acc.y * r, 0.f),
                           fmaxf(acc.z * r, 0.f), fmaxf(acc.w * r, 0.f));

    if (LAYER == 0) {
        __half2 h01 = __floats2half2_rn(o.x, o.y);
        __half2 h23 = __floats2half2_rn(o.z, o.w);
        uint2 u;
        u.x = *reinterpret_cast<unsigned*>(&h01);
        u.y = *reinterpret_cast<unsigned*>(&h23);
        reinterpret_cast<uint2*>(g_x1h + (size_t)node * 128)[lane] = u;
    } else {
        // fused classifier: xc[node] = relu(x2_row) . wc
        float4 w4 = reinterpret_cast<const float4*>(wc)[lane];
        float p = o.x * w4.x;
        p = fmaf(o.y, w4.y, p);
        p = fmaf(o.z, w4.z, p);
        p = fmaf(o.w, w4.w, p);
#pragma unroll
        for (int off = 16; off; off >>= 1)
            p += __shfl_xor_sync(0xffffffffu, p, off);
        if (lane == 0) g_xc[node] = p;
    }
}

// ---------------- final: out[e] = xc[src] + xc[dst] + bc ----------------
__global__ void final_kernel(const int* __restrict__ ei, const float* __restrict__ bc,
                             float* __restrict__ out, int E) {
    int e = blockIdx.x * blockDim.x + threadIdx.x;
    if (e >= E) return;
    out[e] = g_xc[ei[e]] + g_xc[ei[E + e]] + bc[0];
}

// ---------------- launch ----------------
extern "C" void kernel_launch(void* const* d_in, const int* in_sizes, int n_in,
                              void* d_out, int out_size) {
    const int*   ei  = (const int*)  d_in[0];
    const float* ea  = (const float*)d_in[1];
    const float* emb = (const float*)d_in[3];
    const float *wq1 = (const float*)d_in[4],  *bq1 = (const float*)d_in[5];
    const float *wk1 = (const float*)d_in[6],  *bk1 = (const float*)d_in[7];
    const float *wv1 = (const float*)d_in[8],  *bv1 = (const float*)d_in[9];
    const float *wt1 = (const float*)d_in[10], *bt1 = (const float*)d_in[11];
    const float *wq2 = (const float*)d_in[12], *bq2 = (const float*)d_in[13];
    const float *wk2 = (const float*)d_in[14], *bk2 = (const float*)d_in[15];
    const float *wv2 = (const float*)d_in[16], *bv2 = (const float*)d_in[17];
    const float *wt2 = (const float*)d_in[18], *bt2 = (const float*)d_in[19];
    const float *wc  = (const float*)d_in[20], *bc  = (const float*)d_in[21];
    float* out = (float*)d_out;

    int E = in_sizes[0] / 2;

    // conversions (independent of sort chain)
    conv_emb_kernel<<<(N_NODES * 64 + 255) / 256, 256>>>(emb);
    convw_kernel<0><<<(3 * 64 * 128 + 255) / 256, 256>>>(wq1, wk1, wv1, wt1);
    convw_kernel<1><<<(3 * 128 * 128 + 255) / 256, 256>>>(wq2, wk2, wv2, wt2);

    // counting sort by dst
    zero_kernel<<<(N_NODES + 255) / 256, 256>>>();
    hist_kernel<<<(E + 255) / 256, 256>>>(ei, E);
    scanA_kernel<<<SCAN_BLOCKS, 256>>>(N_NODES);
    scanB_kernel<<<1, 256>>>(SCAN_BLOCKS, N_NODES);
    scanC_kernel<<<SCAN_BLOCKS, 256>>>(N_NODES);
    scatter_kernel<<<(E + 255) / 256, 256>>>(ei, ea, E);

    // layer 1 (x = emb half, D=64)
    node_linear_wmma<0><<<N_PAD / 32, 256>>>(bq1, bk1, bv1, bt1);
    edge_agg_kernel<0><<<(N_NODES + 7) / 8, 256>>>(wc);

    // layer 2 (x = g_x1h, D=128), classifier fused
    node_linear_wmma<1><<<N_PAD / 32, 256>>>(bq2, bk2, bv2, bt2);
    edge_agg_kernel<1><<<(N_NODES + 7) / 8, 256>>>(wc);

    final_kernel<<<(E + 255) / 256, 256>>>(ei, bc, out, E);
}

// round 12
// speedup vs baseline: 1.4188x; 1.0804x over previous
#include <cuda_runtime.h>
#include <cuda_fp16.h>
#include <mma.h>
#include <math.h>
using namespace nvcuda;

#define N_NODES 50000
#define N_PAD   50016     // multiple of 32
#define E_MAX   800000
#define SCAN_BLOCKS 196   // 196*256 = 50176 >= 50000

// div_term[i] = 10^(-i/4) = exp(-i*ln(10000)/16), i = 0..15 (exact table)
__constant__ float c_dv[16] = {
    1.0f, 0.5623413251903491f, 0.31622776601683794f, 0.17782794100389228f,
    0.1f, 0.05623413251903491f, 0.031622776601683794f, 0.017782794100389228f,
    0.01f, 0.005623413251903491f, 0.0031622776601683794f, 0.0017782794100389228f,
    0.001f, 0.0005623413251903491f, 0.00031622776601683794f, 0.00017782794100389228f};

// ---------------- static device scratch (zero-initialized, incl. pad rows) ----------------
// g_deg / g_cur are zero at first call (static init) and re-zeroed by final_kernel
// at the end of EVERY call, so every graph replay sees zeros. Deterministic.
__device__ float  g_q  [N_PAD * 128];
__device__ __half g_kh [N_PAD * 128];
__device__ __half g_vh [N_PAD * 128];
__device__ float  g_qt [N_PAD * 128];
__device__ float  g_qbt[N_PAD * 4];
__device__ __half g_xh [N_PAD * 64];    // emb -> half
__device__ __half g_x1h[N_PAD * 128];   // layer-1 output (half), pad rows stay 0
__device__ float  g_xc [N_NODES];
__device__ __half g_w1 [3 * 64 * 128];  // wq1|wk1|wv1 as half
__device__ __half g_wt1[32 * 128];
__device__ __half g_w2 [3 * 128 * 128];
__device__ __half g_wt2[32 * 128];
__device__ int    g_deg[N_NODES];
__device__ int    g_cur[N_NODES];
__device__ int    g_off[N_NODES + 1];
__device__ int    g_bsum[SCAN_BLOCKS];
__device__ int    g_bpre[SCAN_BLOCKS];
__device__ unsigned long long g_se[E_MAX];  // {src, t-bits} sorted by dst

// ---------------- merged setup: conversions + histogram ----------------
__global__ void setup_kernel(const float* __restrict__ emb,
                             const float* __restrict__ wq1, const float* __restrict__ wk1,
                             const float* __restrict__ wv1, const float* __restrict__ wt1,
                             const float* __restrict__ wq2, const float* __restrict__ wk2,
                             const float* __restrict__ wv2, const float* __restrict__ wt2,
                             const int* __restrict__ ei, int E) {
    int i = blockIdx.x * 256 + threadIdx.x;
    if (i < N_NODES * 64) g_xh[i] = __float2half(emb[i]);
    if (i < E) atomicAdd(&g_deg[ei[E + i]], 1);     // histogram (g_deg pre-zeroed)
    {
        const int per = 64 * 128;
        if (i < 3 * per) {
            const float* s = (i < per) ? wq1 : ((i < 2 * per) ? wk1 : wv1);
            g_w1[i] = __float2half(s[i % per]);
        }
    }
    {
        const int per = 128 * 128;
        if (i < 3 * per) {
            const float* s = (i < per) ? wq2 : ((i < 2 * per) ? wk2 : wv2);
            g_w2[i] = __float2half(s[i % per]);
        }
    }
    if (i < 32 * 128) {
        g_wt1[i] = __float2half(wt1[i]);
        g_wt2[i] = __float2half(wt2[i]);
    }
}

// ---------------- counting sort scan chain ----------------
__global__ void scanA_kernel(int n) {
    __shared__ int sh[256];
    int t = threadIdx.x;
    int i = blockIdx.x * 256 + t;
    int v = (i < n) ? g_deg[i] : 0;
    sh[t] = v;
    __syncthreads();
    for (int o = 1; o < 256; o <<= 1) {
        int u = (t >= o) ? sh[t - o] : 0;
        __syncthreads();
        sh[t] += u;
        __syncthreads();
    }
    if (i < n) g_off[i] = sh[t] - v;
    if (t == 255) g_bsum[blockIdx.x] = sh[255];
}

__global__ void scanB_kernel(int nb, int n) {
    __shared__ int sh[256];
    int t = threadIdx.x;
    int v = (t < nb) ? g_bsum[t] : 0;
    sh[t] = v;
    __syncthreads();
    for (int o = 1; o < 256; o <<= 1) {
        int u = (t >= o) ? sh[t - o] : 0;
        __syncthreads();
        sh[t] += u;
        __syncthreads();
    }
    if (t < nb) g_bpre[t] = sh[t] - v;
    if (t == 255) g_off[n] = sh[255];
}

__global__ void scanC_kernel(int n) {
    int i = blockIdx.x * 256 + threadIdx.x;
    if (i < n) g_off[i] += g_bpre[blockIdx.x];
}

__global__ void scatter_kernel(const int* __restrict__ ei,
                               const float* __restrict__ ea, int E) {
    int e = blockIdx.x * blockDim.x + threadIdx.x;
    if (e >= E) return;
    int d = ei[E + e];
    int pos = g_off[d] + atomicAdd(&g_cur[d], 1);
    g_se[pos] = (unsigned int)ei[e] |
        ((unsigned long long)__float_as_uint(ea[2 * e + 1]) << 32);
}

// ---------------- tensor-core node linear: q, k(fp16), v(fp16), qt, qbt ----------------
template <int L>
__global__ __launch_bounds__(256) void node_linear_wmma(
    const float* __restrict__ bq, const float* __restrict__ bk,
    const float* __restrict__ bv, const float* __restrict__ bt)
{
    constexpr int D = (L == 0) ? 64 : 128;
    const __half* __restrict__ xh  = (L == 0) ? g_xh  : g_x1h;
    const __half* __restrict__ wh  = (L == 0) ? g_w1  : g_w2;
    const __half* __restrict__ wth = (L == 0) ? g_wt1 : g_wt2;

    __shared__ float  stage[32 * 128];   // 16 KB
    __shared__ __half qsh[32 * 128];     // 8 KB
    const int w = threadIdx.x >> 5;
    const int node0 = blockIdx.x * 32;

    wmma::fragment<wmma::accumulator, 16, 16, 16, float> acc[3][2];
#pragma unroll
    for (int m = 0; m < 3; m++)
#pragma unroll
        for (int r = 0; r < 2; r++) wmma::fill_fragment(acc[m][r], 0.f);

#pragma unroll
    for (int k0 = 0; k0 < D; k0 += 16) {
        wmma::fragment<wmma::matrix_a, 16, 16, 16, __half, wmma::row_major> a0, a1;
        wmma::load_matrix_sync(a0, xh + (size_t)node0 * D + k0, D);
        wmma::load_matrix_sync(a1, xh + (size_t)(node0 + 16) * D + k0, D);
#pragma unroll
        for (int m = 0; m < 3; m++) {
            wmma::fragment<wmma::matrix_b, 16, 16, 16, __half, wmma::row_major> b;
            wmma::load_matrix_sync(b, wh + m * (D * 128) + k0 * 128 + w * 16, 128);
            wmma::mma_sync(acc[m][0], a0, b, acc[m][0]);
            wmma::mma_sync(acc[m][1], a1, b, acc[m][1]);
        }
    }

    const float inv = 0.17677669529663688f;  // 1/sqrt(32)
#pragma unroll
    for (int m = 0; m < 3; m++) {
        wmma::store_matrix_sync(stage + w * 16, acc[m][0], 128, wmma::mem_row_major);
        wmma::store_matrix_sync(stage + 16 * 128 + w * 16, acc[m][1], 128, wmma::mem_row_major);
        __syncthreads();
        for (int i = threadIdx.x; i < 32 * 128; i += 256) {
            int c = i & 127;
            int node = node0 + (i >> 7);
            float val = stage[i];
            if (m == 0) {
                float qv = (val + bq[c]) * inv;
                qsh[i] = __float2half(qv);
                g_q[(size_t)node * 128 + c] = qv;
            } else if (m == 1) {
                g_kh[(size_t)node * 128 + c] = __float2half(val + bk[c]);
            } else {
                g_vh[(size_t)node * 128 + c] = __float2half(val + bv[c]);
            }
        }
        __syncthreads();
    }

    // qt GEMM: per-head 32x32; warp w -> head h = w>>1, col offset d0 = (w&1)*16
    {
        int h = w >> 1, d0 = (w & 1) * 16;
        wmma::fragment<wmma::accumulator, 16, 16, 16, float> q0, q1;
        wmma::fill_fragment(q0, 0.f);
        wmma::fill_fragment(q1, 0.f);
#pragma unroll
        for (int k0 = 0; k0 < 32; k0 += 16) {
            wmma::fragment<wmma::matrix_a, 16, 16, 16, __half, wmma::row_major> a0, a1;
            wmma::fragment<wmma::matrix_b, 16, 16, 16, __half, wmma::col_major> b;
            wmma::load_matrix_sync(a0, qsh + h * 32 + k0, 128);
            wmma::load_matrix_sync(a1, qsh + 16 * 128 + h * 32 + k0, 128);
            wmma::load_matrix_sync(b, wth + h * 32 + k0 + d0 * 128, 128);
            wmma::mma_sync(q0, a0, b, q0);
            wmma::mma_sync(q1, a1, b, q1);
        }
        wmma::store_matrix_sync(g_qt + (size_t)node0 * 128 + h * 32 + d0, q0, 128, wmma::mem_row_major);
        wmma::store_matrix_sync(g_qt + (size_t)(node0 + 16) * 128 + h * 32 + d0, q1, 128, wmma::mem_row_major);
    }

    // qbt: node n, head hh -> dot(q'[n, hh*32:+32], bt[hh*32:+32])
    if (threadIdx.x < 128) {
        int n = threadIdx.x >> 2, hh = threadIdx.x & 3;
        float b = 0.f;
#pragma unroll
        for (int c = 0; c < 32; c++)
            b = fmaf(__half2float(qsh[n * 128 + hh * 32 + c]), bt[hh * 32 + c], b);
        g_qbt[(size_t)(node0 + n) * 4 + hh] = b;
    }
}

// ---------------- per-node softmax aggregation (warp = node, 4 heads) ----------------
__device__ __forceinline__ float head_alpha(float4 q4, float4 qt4,
                                            float2 k01, float2 k23,
                                            float t, float dva, float dvb) {
    float a0 = t * dva, a1 = t * dvb;
    float p = q4.x * k01.x;
    p = fmaf(q4.y,  k01.y, p);
    p = fmaf(q4.z,  k23.x, p);
    p = fmaf(q4.w,  k23.y, p);
    p = fmaf(qt4.x, __sinf(a0), p);
    p = fmaf(qt4.y, __cosf(a0), p);
    p = fmaf(qt4.z, __sinf(a1), p);
    p = fmaf(qt4.w, __cosf(a1), p);
    p += __shfl_xor_sync(0xffffffffu, p, 4);
    p += __shfl_xor_sync(0xffffffffu, p, 2);
    p += __shfl_xor_sync(0xffffffffu, p, 1);
    return p;
}

template <int LAYER>
__global__ __launch_bounds__(128) void edge_agg_kernel(const float* __restrict__ wc) {
    int lane = threadIdx.x & 31;
    int node = blockIdx.x * 4 + (threadIdx.x >> 5);
    if (node >= N_NODES) return;

    int idx = g_off[node], end = g_off[node + 1];
    if (idx >= end) {
        if (LAYER == 0) {
            reinterpret_cast<uint2*>(g_x1h + (size_t)node * 128)[lane] = make_uint2(0u, 0u);
        } else if (lane == 0) {
            g_xc[node] = 0.f;
        }
        return;
    }

    float4 q4  = reinterpret_cast<const float4*>(g_q  + (size_t)node * 128)[lane];
    float4 qt4 = reinterpret_cast<const float4*>(g_qt + (size_t)node * 128)[lane];
    float qbt  = g_qbt[(size_t)node * 4 + (lane >> 3)];

    int j = lane & 7;
    float dva = c_dv[2 * j];
    float dvb = c_dv[2 * j + 1];

    const float2* kh = reinterpret_cast<const float2*>(g_kh);
    const float2* vh = reinterpret_cast<const float2*>(g_vh);

    float s;
    float4 acc;
    float qbtr;   // qbt - ref, folded
    {   // peel first edge: reference point for exp
        unsigned long long se = g_se[idx];
        int cs = (int)(unsigned int)se;
        float t = __uint_as_float((unsigned int)(se >> 32));
        float2 kraw = kh[(size_t)cs * 32 + lane];
        float2 vraw = vh[(size_t)cs * 32 + lane];
        float2 k01 = __half22float2(*reinterpret_cast<__half2*>(&kraw.x));
        float2 k23 = __half22float2(*reinterpret_cast<__half2*>(&kraw.y));
        float2 v01 = __half22float2(*reinterpret_cast<__half2*>(&vraw.x));
        float2 v23 = __half22float2(*reinterpret_cast<__half2*>(&vraw.y));
        float ref = head_alpha(q4, qt4, k01, k23, t, dva, dvb) + qbt;
        qbtr = qbt - ref;
        s = 1.f;
        acc = make_float4(v01.x, v01.y, v23.x, v23.y);
    }
    idx++;

    unsigned long long nse = 0;
    if (idx < end) nse = g_se[idx];   // prefetch
#pragma unroll 2
    for (; idx < end; idx++) {
        unsigned long long cse = nse;
        if (idx + 1 < end) nse = g_se[idx + 1];
        int   ccs = (int)(unsigned int)cse;
        float ct  = __uint_as_float((unsigned int)(cse >> 32));
        float2 kraw = kh[(size_t)ccs * 32 + lane];
        float2 vraw = vh[(size_t)ccs * 32 + lane];
        float2 k01 = __half22float2(*reinterpret_cast<__half2*>(&kraw.x));
        float2 k23 = __half22float2(*reinterpret_cast<__half2*>(&kraw.y));
        float2 v01 = __half22float2(*reinterpret_cast<__half2*>(&vraw.x));
        float2 v23 = __half22float2(*reinterpret_cast<__half2*>(&vraw.y));
        float alpha = head_alpha(q4, qt4, k01, k23, ct, dva, dvb) + qbtr;
        float pe = __expf(fminf(alpha, 80.f));
        s += pe;
        acc.x = fmaf(pe, v01.x, acc.x);
        acc.y = fmaf(pe, v01.y, acc.y);
        acc.z = fmaf(pe, v23.x, acc.z);
        acc.w = fmaf(pe, v23.y, acc.w);
    }

    float r = 1.f / s;
    float4 o = make_float4(fmaxf(acc.x * r, 0.f), fmaxf(acc.y * r, 0.f),
                           fmaxf(acc.z * r, 0.f), fmaxf(acc.w * r, 0.f));

    if (LAYER == 0) {
        __half2 h01 = __floats2half2_rn(o.x, o.y);
        __half2 h23 = __floats2half2_rn(o.z, o.w);
        uint2 u;
        u.x = *reinterpret_cast<unsigned*>(&h01);
        u.y = *reinterpret_cast<unsigned*>(&h23);
        reinterpret_cast<uint2*>(g_x1h + (size_t)node * 128)[lane] = u;
    } else {
        // fused classifier: xc[node] = relu(x2_row) . wc
        float4 w4 = reinterpret_cast<const float4*>(wc)[lane];
        float p = o.x * w4.x;
        p = fmaf(o.y, w4.y, p);
        p = fmaf(o.z, w4.z, p);
        p = fmaf(o.w, w4.w, p);
#pragma unroll
        for (int off = 16; off; off >>= 1)
            p += __shfl_xor_sync(0xffffffffu, p, off);
        if (lane == 0) g_xc[node] = p;
    }
}

// ---------------- final: out[e] = xc[src] + xc[dst] + bc ; re-zero counters ----------------
__global__ void final_kernel(const int* __restrict__ ei, const float* __restrict__ bc,
                             float* __restrict__ out, int E) {
    int e = blockIdx.x * blockDim.x + threadIdx.x;
    if (e < N_NODES) { g_deg[e] = 0; g_cur[e] = 0; }   // ready for next replay
    if (e >= E) return;
    out[e] = g_xc[ei[e]] + g_xc[ei[E + e]] + bc[0];
}

// ---------------- launch (capture fork/join for overlap) ----------------
extern "C" void kernel_launch(void* const* d_in, const int* in_sizes, int n_in,
                              void* d_out, int out_size) {
    const int*   ei  = (const int*)  d_in[0];
    const float* ea  = (const float*)d_in[1];
    const float* emb = (const float*)d_in[3];
    const float *wq1 = (const float*)d_in[4],  *bq1 = (const float*)d_in[5];
    const float *wk1 = (const float*)d_in[6],  *bk1 = (const float*)d_in[7];
    const float *wv1 = (const float*)d_in[8],  *bv1 = (const float*)d_in[9];
    const float *wt1 = (const float*)d_in[10], *bt1 = (const float*)d_in[11];
    const float *wq2 = (const float*)d_in[12], *bq2 = (const float*)d_in[13];
    const float *wk2 = (const float*)d_in[14], *bk2 = (const float*)d_in[15];
    const float *wv2 = (const float*)d_in[16], *bv2 = (const float*)d_in[17];
    const float *wt2 = (const float*)d_in[18], *bt2 = (const float*)d_in[19];
    const float *wc  = (const float*)d_in[20], *bc  = (const float*)d_in[21];
    float* out = (float*)d_out;

    int E = in_sizes[0] / 2;

    // Fresh side stream + events each call (deterministic; intentionally leaked —
    // kernel_launch runs only a handful of times, and these are host-side objects).
    cudaStream_t s2;
    cudaStreamCreateWithFlags(&s2, cudaStreamNonBlocking);
    cudaEvent_t ev1, ev2;
    cudaEventCreateWithFlags(&ev1, cudaEventDisableTiming);
    cudaEventCreateWithFlags(&ev2, cudaEventDisableTiming);

    // setup: conversions + histogram (g_deg zeroed by previous call's final_kernel)
    setup_kernel<<<(N_NODES * 64 + 255) / 256, 256>>>(emb, wq1, wk1, wv1, wt1,
                                                      wq2, wk2, wv2, wt2, ei, E);

    // fork: sort chain on s2, node_linear<0> on main stream (independent)
    cudaEventRecord(ev1, 0);
    cudaStreamWaitEvent(s2, ev1, 0);
    scanA_kernel<<<SCAN_BLOCKS, 256, 0, s2>>>(N_NODES);
    scanB_kernel<<<1, 256, 0, s2>>>(SCAN_BLOCKS, N_NODES);
    scanC_kernel<<<SCAN_BLOCKS, 256, 0, s2>>>(N_NODES);
    scatter_kernel<<<(E + 255) / 256, 256, 0, s2>>>(ei, ea, E);
    cudaEventRecord(ev2, s2);

    node_linear_wmma<0><<<N_PAD / 32, 256>>>(bq1, bk1, bv1, bt1);

    // join: edge_agg<0> needs both scatter and node_linear<0>
    cudaStreamWaitEvent(0, ev2, 0);
    edge_agg_kernel<0><<<(N_NODES + 3) / 4, 128>>>(wc);

    node_linear_wmma<1><<<N_PAD / 32, 256>>>(bq2, bk2, bv2, bt2);
    edge_agg_kernel<1><<<(N_NODES + 3) / 4, 128>>>(wc);

    final_kernel<<<(E + 255) / 256, 256>>>(ei, bc, out, E);
}

// round 13
// speedup vs baseline: 1.5060x; 1.0615x over previous
#include <cuda_runtime.h>
#include <cuda_fp16.h>
#include <mma.h>
#include <math.h>
using namespace nvcuda;

#define N_NODES 50000
#define N_PAD   50016     // multiple of 32
#define E_MAX   800000
#define SCAN_BLOCKS 196   // 196*256 = 50176 >= 50000

// div_term[i] = 10^(-i/4) = exp(-i*ln(10000)/16), i = 0..15 (exact table)
__constant__ float c_dv[16] = {
    1.0f, 0.5623413251903491f, 0.31622776601683794f, 0.17782794100389228f,
    0.1f, 0.05623413251903491f, 0.031622776601683794f, 0.017782794100389228f,
    0.01f, 0.005623413251903491f, 0.0031622776601683794f, 0.0017782794100389228f,
    0.001f, 0.0005623413251903491f, 0.00031622776601683794f, 0.00017782794100389228f};

// ---------------- static device scratch (zero-initialized, incl. pad rows) ----------------
// g_deg / g_cur are zero at first call (static init) and re-zeroed by final_kernel
// at the end of EVERY call, so every graph replay sees zeros. Deterministic.
__device__ float  g_q  [N_PAD * 128];
__device__ __half g_kh [N_PAD * 128];
__device__ __half g_vh [N_PAD * 128];
__device__ float  g_qt [N_PAD * 128];
__device__ float  g_qbt[N_PAD * 4];
__device__ __half g_xh [N_PAD * 64];    // emb -> half
__device__ __half g_x1h[N_PAD * 128];   // layer-1 output (half), pad rows stay 0
__device__ float  g_xc [N_NODES];
__device__ __half g_w1 [3 * 64 * 128];  // wq1|wk1|wv1 as half
__device__ __half g_wt1[32 * 128];
__device__ __half g_w2 [3 * 128 * 128];
__device__ __half g_wt2[32 * 128];
__device__ int    g_deg[N_NODES];
__device__ int    g_cur[N_NODES];
__device__ int    g_off[N_NODES + 1];
__device__ int    g_bsum[SCAN_BLOCKS];
__device__ int    g_bpre[SCAN_BLOCKS];
__device__ unsigned long long g_se[E_MAX];  // {src, t-bits} sorted by dst

// ---------------- merged setup: conversions + histogram ----------------
__global__ void setup_kernel(const float* __restrict__ emb,
                             const float* __restrict__ wq1, const float* __restrict__ wk1,
                             const float* __restrict__ wv1, const float* __restrict__ wt1,
                             const float* __restrict__ wq2, const float* __restrict__ wk2,
                             const float* __restrict__ wv2, const float* __restrict__ wt2,
                             const int* __restrict__ ei, int E) {
    int i = blockIdx.x * 256 + threadIdx.x;
    if (i < N_NODES * 64) g_xh[i] = __float2half(emb[i]);
    if (i < E) atomicAdd(&g_deg[ei[E + i]], 1);     // histogram (g_deg pre-zeroed)
    {
        const int per = 64 * 128;
        if (i < 3 * per) {
            const float* s = (i < per) ? wq1 : ((i < 2 * per) ? wk1 : wv1);
            g_w1[i] = __float2half(s[i % per]);
        }
    }
    {
        const int per = 128 * 128;
        if (i < 3 * per) {
            const float* s = (i < per) ? wq2 : ((i < 2 * per) ? wk2 : wv2);
            g_w2[i] = __float2half(s[i % per]);
        }
    }
    if (i < 32 * 128) {
        g_wt1[i] = __float2half(wt1[i]);
        g_wt2[i] = __float2half(wt2[i]);
    }
}

// ---------------- counting sort scan chain ----------------
__global__ void scanA_kernel(int n) {
    __shared__ int sh[256];
    int t = threadIdx.x;
    int i = blockIdx.x * 256 + t;
    int v = (i < n) ? g_deg[i] : 0;
    sh[t] = v;
    __syncthreads();
    for (int o = 1; o < 256; o <<= 1) {
        int u = (t >= o) ? sh[t - o] : 0;
        __syncthreads();
        sh[t] += u;
        __syncthreads();
    }
    if (i < n) g_off[i] = sh[t] - v;
    if (t == 255) g_bsum[blockIdx.x] = sh[255];
}

__global__ void scanB_kernel(int nb, int n) {
    __shared__ int sh[256];
    int t = threadIdx.x;
    int v = (t < nb) ? g_bsum[t] : 0;
    sh[t] = v;
    __syncthreads();
    for (int o = 1; o < 256; o <<= 1) {
        int u = (t >= o) ? sh[t - o] : 0;
        __syncthreads();
        sh[t] += u;
        __syncthreads();
    }
    if (t < nb) g_bpre[t] = sh[t] - v;
    if (t == 255) g_off[n] = sh[255];
}

__global__ void scanC_kernel(int n) {
    int i = blockIdx.x * 256 + threadIdx.x;
    if (i < n) g_off[i] += g_bpre[blockIdx.x];
}

__global__ void scatter_kernel(const int* __restrict__ ei,
                               const float* __restrict__ ea, int E) {
    int e = blockIdx.x * blockDim.x + threadIdx.x;
    if (e >= E) return;
    int d = ei[E + e];
    int pos = g_off[d] + atomicAdd(&g_cur[d], 1);
    g_se[pos] = (unsigned int)ei[e] |
        ((unsigned long long)__float_as_uint(ea[2 * e + 1]) << 32);
}

// ---------------- tensor-core node linear: q, k(fp16), v(fp16), qt, qbt ----------------
template <int L>
__global__ __launch_bounds__(256) void node_linear_wmma(
    const float* __restrict__ bq, const float* __restrict__ bk,
    const float* __restrict__ bv, const float* __restrict__ bt)
{
    constexpr int D = (L == 0) ? 64 : 128;
    const __half* __restrict__ xh  = (L == 0) ? g_xh  : g_x1h;
    const __half* __restrict__ wh  = (L == 0) ? g_w1  : g_w2;
    const __half* __restrict__ wth = (L == 0) ? g_wt1 : g_wt2;

    __shared__ float  stage[32 * 128];   // 16 KB
    __shared__ __half qsh[32 * 128];     // 8 KB
    const int w = threadIdx.x >> 5;
    const int node0 = blockIdx.x * 32;

    wmma::fragment<wmma::accumulator, 16, 16, 16, float> acc[3][2];
#pragma unroll
    for (int m = 0; m < 3; m++)
#pragma unroll
        for (int r = 0; r < 2; r++) wmma::fill_fragment(acc[m][r], 0.f);

#pragma unroll
    for (int k0 = 0; k0 < D; k0 += 16) {
        wmma::fragment<wmma::matrix_a, 16, 16, 16, __half, wmma::row_major> a0, a1;
        wmma::load_matrix_sync(a0, xh + (size_t)node0 * D + k0, D);
        wmma::load_matrix_sync(a1, xh + (size_t)(node0 + 16) * D + k0, D);
#pragma unroll
        for (int m = 0; m < 3; m++) {
            wmma::fragment<wmma::matrix_b, 16, 16, 16, __half, wmma::row_major> b;
            wmma::load_matrix_sync(b, wh + m * (D * 128) + k0 * 128 + w * 16, 128);
            wmma::mma_sync(acc[m][0], a0, b, acc[m][0]);
            wmma::mma_sync(acc[m][1], a1, b, acc[m][1]);
        }
    }

    const float inv = 0.17677669529663688f;  // 1/sqrt(32)
#pragma unroll
    for (int m = 0; m < 3; m++) {
        wmma::store_matrix_sync(stage + w * 16, acc[m][0], 128, wmma::mem_row_major);
        wmma::store_matrix_sync(stage + 16 * 128 + w * 16, acc[m][1], 128, wmma::mem_row_major);
        __syncthreads();
        for (int i = threadIdx.x; i < 32 * 128; i += 256) {
            int c = i & 127;
            int node = node0 + (i >> 7);
            float val = stage[i];
            if (m == 0) {
                float qv = (val + bq[c]) * inv;
                qsh[i] = __float2half(qv);
                g_q[(size_t)node * 128 + c] = qv;
            } else if (m == 1) {
                g_kh[(size_t)node * 128 + c] = __float2half(val + bk[c]);
            } else {
                g_vh[(size_t)node * 128 + c] = __float2half(val + bv[c]);
            }
        }
        __syncthreads();
    }

    // qt GEMM: per-head 32x32; warp w -> head h = w>>1, col offset d0 = (w&1)*16
    {
        int h = w >> 1, d0 = (w & 1) * 16;
        wmma::fragment<wmma::accumulator, 16, 16, 16, float> q0, q1;
        wmma::fill_fragment(q0, 0.f);
        wmma::fill_fragment(q1, 0.f);
#pragma unroll
        for (int k0 = 0; k0 < 32; k0 += 16) {
            wmma::fragment<wmma::matrix_a, 16, 16, 16, __half, wmma::row_major> a0, a1;
            wmma::fragment<wmma::matrix_b, 16, 16, 16, __half, wmma::col_major> b;
            wmma::load_matrix_sync(a0, qsh + h * 32 + k0, 128);
            wmma::load_matrix_sync(a1, qsh + 16 * 128 + h * 32 + k0, 128);
            wmma::load_matrix_sync(b, wth + h * 32 + k0 + d0 * 128, 128);
            wmma::mma_sync(q0, a0, b, q0);
            wmma::mma_sync(q1, a1, b, q1);
        }
        wmma::store_matrix_sync(g_qt + (size_t)node0 * 128 + h * 32 + d0, q0, 128, wmma::mem_row_major);
        wmma::store_matrix_sync(g_qt + (size_t)(node0 + 16) * 128 + h * 32 + d0, q1, 128, wmma::mem_row_major);
    }

    // qbt: node n, head hh -> dot(q'[n, hh*32:+32], bt[hh*32:+32])
    if (threadIdx.x < 128) {
        int n = threadIdx.x >> 2, hh = threadIdx.x & 3;
        float b = 0.f;
#pragma unroll
        for (int c = 0; c < 32; c++)
            b = fmaf(__half2float(qsh[n * 128 + hh * 32 + c]), bt[hh * 32 + c], b);
        g_qbt[(size_t)(node0 + n) * 4 + hh] = b;
    }
}

// ---------------- per-node softmax aggregation ----------------
// Mapping: warp = node; half = lane>>4 picks one of 2 edges per iteration;
// sl = lane&15 owns output dims [sl*8, sl*8+8) (head h = sl>>2, m = sl&3).
// Each lane: 16-FMA dot slice over its 8 k-dims + 8 tf-dims, 2-shfl reduce over
// the 4-lane head group, raw exp (alphas O(0.1); shift-free validated R10),
// 8-dim v accumulation. Halves merged once at the end.
template <int LAYER>
__global__ __launch_bounds__(128) void edge_agg_kernel(const float* __restrict__ wc) {
    const int lane = threadIdx.x & 31;
    const int node = blockIdx.x * 4 + (threadIdx.x >> 5);
    if (node >= N_NODES) return;

    const int sl   = lane & 15;
    const int half = lane >> 4;
    const int D0   = sl * 8;        // output dims owned
    const int h    = sl >> 2;       // head
    const int m    = sl & 3;        // slice within head

    const int start = g_off[node], end = g_off[node + 1];
    if (start >= end) {
        if (LAYER == 0) {
            if (half == 0)
                *reinterpret_cast<uint4*>(g_x1h + (size_t)node * 128 + D0) =
                    make_uint4(0u, 0u, 0u, 0u);
        } else if (lane == 0) {
            g_xc[node] = 0.f;
        }
        return;
    }

    // distributed q/qt: 8 floats each (dims D0..D0+7)
    const float4* qp  = reinterpret_cast<const float4*>(g_q  + (size_t)node * 128 + D0);
    const float4* qtp = reinterpret_cast<const float4*>(g_qt + (size_t)node * 128 + D0);
    float4 qa = qp[0],  qb = qp[1];
    float4 ta = qtp[0], tb = qtp[1];
    const float qbt = g_qbt[(size_t)node * 4 + h];

    // loop-invariant frequencies for this lane's 4 (sin,cos) pairs
    const float dv0 = c_dv[m * 4 + 0];
    const float dv1 = c_dv[m * 4 + 1];
    const float dv2 = c_dv[m * 4 + 2];
    const float dv3 = c_dv[m * 4 + 3];

    float a0 = 0.f, a1 = 0.f, a2 = 0.f, a3 = 0.f;
    float a4 = 0.f, a5 = 0.f, a6 = 0.f, a7 = 0.f;
    float s = 0.f;

    for (int base = start; base < end; base += 2) {
        int e = base + half;
        bool valid = e < end;
        int ce = valid ? e : end - 1;
        unsigned long long se = g_se[ce];
        int   src = (int)(unsigned int)se;
        float tv  = __uint_as_float((unsigned int)(se >> 32));

        uint4 kk = *reinterpret_cast<const uint4*>(g_kh + (size_t)src * 128 + D0);
        uint4 vv = *reinterpret_cast<const uint4*>(g_vh + (size_t)src * 128 + D0);

        float2 k0 = __half22float2(*reinterpret_cast<__half2*>(&kk.x));
        float2 k1 = __half22float2(*reinterpret_cast<__half2*>(&kk.y));
        float2 k2 = __half22float2(*reinterpret_cast<__half2*>(&kk.z));
        float2 k3 = __half22float2(*reinterpret_cast<__half2*>(&kk.w));

        float p = qa.x * k0.x;
        p = fmaf(qa.y, k0.y, p); p = fmaf(qa.z, k1.x, p); p = fmaf(qa.w, k1.y, p);
        p = fmaf(qb.x, k2.x, p); p = fmaf(qb.y, k2.y, p);
        p = fmaf(qb.z, k3.x, p); p = fmaf(qb.w, k3.y, p);

        float g0 = tv * dv0, g1 = tv * dv1, g2 = tv * dv2, g3 = tv * dv3;
        p = fmaf(ta.x, __sinf(g0), p); p = fmaf(ta.y, __cosf(g0), p);
        p = fmaf(ta.z, __sinf(g1), p); p = fmaf(ta.w, __cosf(g1), p);
        p = fmaf(tb.x, __sinf(g2), p); p = fmaf(tb.y, __cosf(g2), p);
        p = fmaf(tb.z, __sinf(g3), p); p = fmaf(tb.w, __cosf(g3), p);

        // reduce over the 4-lane head group (bits 0-1 of lane)
        p += __shfl_xor_sync(0xffffffffu, p, 1);
        p += __shfl_xor_sync(0xffffffffu, p, 2);
        float alpha = p + qbt;
        float pe = valid ? __expf(fminf(alpha, 80.f)) : 0.f;

        float2 v0 = __half22float2(*reinterpret_cast<__half2*>(&vv.x));
        float2 v1 = __half22float2(*reinterpret_cast<__half2*>(&vv.y));
        float2 v2 = __half22float2(*reinterpret_cast<__half2*>(&vv.z));
        float2 v3 = __half22float2(*reinterpret_cast<__half2*>(&vv.w));

        s += pe;
        a0 = fmaf(pe, v0.x, a0); a1 = fmaf(pe, v0.y, a1);
        a2 = fmaf(pe, v1.x, a2); a3 = fmaf(pe, v1.y, a3);
        a4 = fmaf(pe, v2.x, a4); a5 = fmaf(pe, v2.y, a5);
        a6 = fmaf(pe, v3.x, a6); a7 = fmaf(pe, v3.y, a7);
    }

    // merge the two edge-halves (lane i <-> lane i^16)
    s  += __shfl_xor_sync(0xffffffffu, s,  16);
    a0 += __shfl_xor_sync(0xffffffffu, a0, 16);
    a1 += __shfl_xor_sync(0xffffffffu, a1, 16);
    a2 += __shfl_xor_sync(0xffffffffu, a2, 16);
    a3 += __shfl_xor_sync(0xffffffffu, a3, 16);
    a4 += __shfl_xor_sync(0xffffffffu, a4, 16);
    a5 += __shfl_xor_sync(0xffffffffu, a5, 16);
    a6 += __shfl_xor_sync(0xffffffffu, a6, 16);
    a7 += __shfl_xor_sync(0xffffffffu, a7, 16);

    float r = 1.f / (s + 1e-37f);
    float o0 = fmaxf(a0 * r, 0.f), o1 = fmaxf(a1 * r, 0.f);
    float o2 = fmaxf(a2 * r, 0.f), o3 = fmaxf(a3 * r, 0.f);
    float o4 = fmaxf(a4 * r, 0.f), o5 = fmaxf(a5 * r, 0.f);
    float o6 = fmaxf(a6 * r, 0.f), o7 = fmaxf(a7 * r, 0.f);

    if (LAYER == 0) {
        if (half == 0) {
            __half2 h0 = __floats2half2_rn(o0, o1);
            __half2 h1 = __floats2half2_rn(o2, o3);
            __half2 h2 = __floats2half2_rn(o4, o5);
            __half2 h3 = __floats2half2_rn(o6, o7);
            uint4 u;
            u.x = *reinterpret_cast<unsigned*>(&h0);
            u.y = *reinterpret_cast<unsigned*>(&h1);
            u.z = *reinterpret_cast<unsigned*>(&h2);
            u.w = *reinterpret_cast<unsigned*>(&h3);
            *reinterpret_cast<uint4*>(g_x1h + (size_t)node * 128 + D0) = u;
        }
    } else {
        // fused classifier: xc[node] = relu(x2_row) . wc
        const float4* wp = reinterpret_cast<const float4*>(wc + D0);
        float4 wa = wp[0], wb = wp[1];
        float p = o0 * wa.x;
        p = fmaf(o1, wa.y, p); p = fmaf(o2, wa.z, p); p = fmaf(o3, wa.w, p);
        p = fmaf(o4, wb.x, p); p = fmaf(o5, wb.y, p);
        p = fmaf(o6, wb.z, p); p = fmaf(o7, wb.w, p);
        // sum over sl = 0..15 (both halves hold identical copies)
        p += __shfl_xor_sync(0xffffffffu, p, 1);
        p += __shfl_xor_sync(0xffffffffu, p, 2);
        p += __shfl_xor_sync(0xffffffffu, p, 4);
        p += __shfl_xor_sync(0xffffffffu, p, 8);
        if (lane == 0) g_xc[node] = p;
    }
}

// ---------------- final: out[e] = xc[src] + xc[dst] + bc ; re-zero counters ----------------
__global__ void final_kernel(const int* __restrict__ ei, const float* __restrict__ bc,
                             float* __restrict__ out, int E) {
    int e = blockIdx.x * blockDim.x + threadIdx.x;
    if (e < N_NODES) { g_deg[e] = 0; g_cur[e] = 0; }   // ready for next replay
    if (e >= E) return;
    out[e] = g_xc[ei[e]] + g_xc[ei[E + e]] + bc[0];
}

// ---------------- launch (capture fork/join for overlap) ----------------
extern "C" void kernel_launch(void* const* d_in, const int* in_sizes, int n_in,
                              void* d_out, int out_size) {
    const int*   ei  = (const int*)  d_in[0];
    const float* ea  = (const float*)d_in[1];
    const float* emb = (const float*)d_in[3];
    const float *wq1 = (const float*)d_in[4],  *bq1 = (const float*)d_in[5];
    const float *wk1 = (const float*)d_in[6],  *bk1 = (const float*)d_in[7];
    const float *wv1 = (const float*)d_in[8],  *bv1 = (const float*)d_in[9];
    const float *wt1 = (const float*)d_in[10], *bt1 = (const float*)d_in[11];
    const float *wq2 = (const float*)d_in[12], *bq2 = (const float*)d_in[13];
    const float *wk2 = (const float*)d_in[14], *bk2 = (const float*)d_in[15];
    const float *wv2 = (const float*)d_in[16], *bv2 = (const float*)d_in[17];
    const float *wt2 = (const float*)d_in[18], *bt2 = (const float*)d_in[19];
    const float *wc  = (const float*)d_in[20], *bc  = (const float*)d_in[21];
    float* out = (float*)d_out;

    int E = in_sizes[0] / 2;

    // Fresh side stream + events each call (deterministic; host-side objects,
    // intentionally leaked — kernel_launch runs only a handful of times).
    cudaStream_t s2;
    cudaStreamCreateWithFlags(&s2, cudaStreamNonBlocking);
    cudaEvent_t ev1, ev2;
    cudaEventCreateWithFlags(&ev1, cudaEventDisableTiming);
    cudaEventCreateWithFlags(&ev2, cudaEventDisableTiming);

    // setup: conversions + histogram (g_deg zeroed by previous call's final_kernel)
    setup_kernel<<<(N_NODES * 64 + 255) / 256, 256>>>(emb, wq1, wk1, wv1, wt1,
                                                      wq2, wk2, wv2, wt2, ei, E);

    // fork: sort chain on s2, node_linear<0> on main stream (independent)
    cudaEventRecord(ev1, 0);
    cudaStreamWaitEvent(s2, ev1, 0);
    scanA_kernel<<<SCAN_BLOCKS, 256, 0, s2>>>(N_NODES);
    scanB_kernel<<<1, 256, 0, s2>>>(SCAN_BLOCKS, N_NODES);
    scanC_kernel<<<SCAN_BLOCKS, 256, 0, s2>>>(N_NODES);
    scatter_kernel<<<(E + 255) / 256, 256, 0, s2>>>(ei, ea, E);
    cudaEventRecord(ev2, s2);

    node_linear_wmma<0><<<N_PAD / 32, 256>>>(bq1, bk1, bv1, bt1);

    // join: edge_agg<0> needs both scatter and node_linear<0>
    cudaStreamWaitEvent(0, ev2, 0);
    edge_agg_kernel<0><<<(N_NODES + 3) / 4, 128>>>(wc);

    node_linear_wmma<1><<<N_PAD / 32, 256>>>(bq2, bk2, bv2, bt2);
    edge_agg_kernel<1><<<(N_NODES + 3) / 4, 128>>>(wc);

    final_kernel<<<(E + 255) / 256, 256>>>(ei, bc, out, E);
}